// round 3
// baseline (speedup 1.0000x reference)
#include <cuda_runtime.h>
#include <cstdint>
#include <cstddef>

// ---------------- device scratch (module globals: allocation-free) ----------------
#define NODES_MAX 4096
#define SMAX 64
__device__ int g_order[NODES_MAX];
__device__ int g_segStart[SMAX];
__device__ int g_segCount[SMAX];

// ---------------- grouping kernel: counting sort of nodes by species ----------------
// Per-node output is independent of intra-species ordering, so atomic
// nondeterminism in g_order does NOT affect the final result.
__global__ void group_kernel(const int* __restrict__ index, int N) {
    __shared__ int cnt[SMAX];
    __shared__ int cur[SMAX];
    int tid = threadIdx.x;
    if (tid < SMAX) cnt[tid] = 0;
    __syncthreads();
    for (int i = tid; i < N; i += blockDim.x)
        atomicAdd(&cnt[index[i] & (SMAX - 1)], 1);
    __syncthreads();
    if (tid == 0) {
        int run = 0;
        for (int s = 0; s < SMAX; s++) {
            g_segStart[s] = run;
            g_segCount[s] = cnt[s];
            cur[s] = run;
            run += cnt[s];
        }
    }
    __syncthreads();
    for (int i = tid; i < N; i += blockDim.x) {
        int s = index[i] & (SMAX - 1);
        int p = atomicAdd(&cur[s], 1);
        if (p < NODES_MAX) g_order[p] = i;
    }
}

// ---------------- main kernel ----------------
// grid = (C/8 channel-tiles, S species). Warp w handles channel c0+w.
// Phase 1: build uw[c][j][e] = sum_k u[ab,j,k,il] * w[s,k,c] * mul^-0.25 in smem
//          (e = ab*9 + i_global, 729 values; 6561 floats per channel).
// Phase 2: stream species' nodes in groups of 4; per 32-wide e-tile:
//          9 LDS (conflict-free, amortized over 4 nodes) + 36 FFMA,
//          coalesced STG.32 per node.
#define CT 8
#define UW_F (CT * 6561)          // 52488 floats
#define WS_OFF UW_F
#define SMEM_F (UW_F + 240)       // + ws[30][8]
#define SMEM_BYTES (SMEM_F * 4)   // 210,912 B

__global__ __launch_bounds__(256, 1)
void mace_kernel(const float* __restrict__ nf,
                 const float* __restrict__ u0, const float* __restrict__ u1,
                 const float* __restrict__ u2,
                 const float* __restrict__ w0, const float* __restrict__ w1,
                 const float* __restrict__ w2,
                 float* __restrict__ out, int C) {
    extern __shared__ float sm[];
    float* uw = sm;                 // [8][6561]
    float* ws = sm + WS_OFF;        // [30][8]

    const int s = blockIdx.y;
    const int m = g_segCount[s];
    if (m == 0) return;             // CTA-uniform, before any barrier
    const int c0 = blockIdx.x * CT;
    const int segBase = g_segStart[s];
    const int tid = threadIdx.x;

    // ---- stage scaled species weights: ws[kglobal][c], kglobal in [0,30) ----
    if (tid < 240) {
        int kg = tid >> 3, c = tid & 7;
        const float* wp; int k; float scale; int mul;
        if (kg < 7)       { wp = w0; k = kg;      scale = 0.61478815f; mul = 7;  }
        else if (kg < 18) { wp = w1; k = kg - 7;  scale = 0.54910049f; mul = 11; }
        else              { wp = w2; k = kg - 18; scale = 0.53728497f; mul = 12; }
        ws[tid] = wp[((size_t)s * mul + k) * C + (c0 + c)] * scale;
    }
    __syncthreads();

    // ---- build uw for all 8 channels: item = j*729 + e ----
    for (int item = tid; item < 6561; item += 256) {
        int j  = item / 729;
        int e  = item - j * 729;
        int ab = e / 9;
        int i  = e - ab * 9;
        const float* up; int mul, koff, il, irr;
        if (i == 0)     { up = u0; mul = 7;  koff = 0;  il = 0;     irr = 1; }
        else if (i < 4) { up = u1; mul = 11; koff = 7;  il = i - 1; irr = 3; }
        else            { up = u2; mul = 12; koff = 18; il = i - 4; irr = 5; }
        const float* ub = up + ((size_t)(ab * 9 + j) * mul) * irr + il;
        float acc[8];
        #pragma unroll
        for (int c = 0; c < 8; c++) acc[c] = 0.f;
        for (int k = 0; k < mul; k++) {
            float uk = __ldg(ub + k * irr);
            const float* wr = ws + (koff + k) * 8;
            #pragma unroll
            for (int c = 0; c < 8; c++) acc[c] += uk * wr[c];
        }
        #pragma unroll
        for (int c = 0; c < 8; c++) uw[c * 6561 + item] = acc[c];
    }
    __syncthreads();

    // ---- main loop ----
    const int lane = tid & 31;
    const int cw   = tid >> 5;            // warp = channel within tile
    const int crow = c0 + cw;
    const float* uwC = uw + cw * 6561;

    const int groups = (m + 3) >> 2;
    for (int g = 0; g < groups; g++) {
        // 36 x-values (4 nodes x 9 j). v0 covers elements 0..31 (one per lane),
        // v1 covers elements 32..35 (lanes 0..3). Broadcast via shfl.
        int n0 = lane / 9, j0 = lane - n0 * 9;     // element = lane
        int idx0 = g * 4 + n0;
        if (idx0 >= m) idx0 = m - 1;               // clamp: safe read, store guarded
        int nid = g_order[segBase + idx0];
        float v0 = nf[((size_t)nid * C + crow) * 9 + j0];
        float v1 = 0.f;
        if (lane < 4) {                            // elements 32..35 -> node 3, j=5..8
            int idx1 = g * 4 + 3;
            if (idx1 >= m) idx1 = m - 1;
            int nid1 = g_order[segBase + idx1];
            v1 = nf[((size_t)nid1 * C + crow) * 9 + (5 + lane)];
        }

        float x[4][9];
        float* op[4];
        bool valid[4];
        #pragma unroll
        for (int nd = 0; nd < 4; nd++) {
            int n4 = __shfl_sync(0xffffffffu, nid, nd * 9);
            valid[nd] = (g * 4 + nd) < m;
            op[nd] = out + ((size_t)n4 * C + crow) * 729;
            #pragma unroll
            for (int j = 0; j < 9; j++) {
                int el = nd * 9 + j;
                x[nd][j] = (el < 32) ? __shfl_sync(0xffffffffu, v0, el)
                                     : __shfl_sync(0xffffffffu, v1, el - 32);
            }
        }

        // 729 outputs per node = 23 tiles of 32 lanes
        #pragma unroll 1
        for (int t = 0; t < 23; t++) {
            int e = t * 32 + lane;
            bool act = e < 729;
            int ee = act ? e : 728;
            float a0 = 0.f, a1 = 0.f, a2 = 0.f, a3 = 0.f;
            #pragma unroll
            for (int j = 0; j < 9; j++) {
                float uv = uwC[j * 729 + ee];
                a0 += uv * x[0][j];
                a1 += uv * x[1][j];
                a2 += uv * x[2][j];
                a3 += uv * x[3][j];
            }
            if (act) {
                if (valid[0]) op[0][e] = a0;
                if (valid[1]) op[1][e] = a1;
                if (valid[2]) op[2][e] = a2;
                if (valid[3]) op[3][e] = a3;
            }
        }
    }
}

// ---------------- launch ----------------
extern "C" void kernel_launch(void* const* d_in, const int* in_sizes, int n_in,
                              void* d_out, int out_size) {
    // Identify inputs by element count (all distinct for this problem):
    // nf=2359296, index=2048, u0=5103, u1=24057, u2=43740,
    // w0=44800, w1=70400, w2=76800
    const float *nf = nullptr, *u0 = nullptr, *u1 = nullptr, *u2 = nullptr;
    const float *w0 = nullptr, *w1 = nullptr, *w2 = nullptr;
    const int* index = nullptr;
    int N = 0, nf_sz = 0, w0_sz = 0;
    for (int i = 0; i < n_in; i++) {
        int sz = in_sizes[i];
        switch (sz) {
            case 5103:    u0 = (const float*)d_in[i]; break;
            case 24057:   u1 = (const float*)d_in[i]; break;
            case 43740:   u2 = (const float*)d_in[i]; break;
            case 44800:   w0 = (const float*)d_in[i]; w0_sz = sz; break;
            case 70400:   w1 = (const float*)d_in[i]; break;
            case 76800:   w2 = (const float*)d_in[i]; break;
            case 2048:    index = (const int*)d_in[i]; N = sz; break;
            case 2359296: nf = (const float*)d_in[i]; nf_sz = sz; break;
            default: break;
        }
    }
    if (!nf || !index || !u0 || !u1 || !u2 || !w0 || !w1 || !w2) return;

    const int C = nf_sz / (N * 9);        // 128
    const int S = w0_sz / (7 * C);        // 50

    group_kernel<<<1, 256>>>(index, N);

    cudaFuncSetAttribute(mace_kernel,
                         cudaFuncAttributeMaxDynamicSharedMemorySize, SMEM_BYTES);
    dim3 grid(C / CT, S);
    mace_kernel<<<grid, 256, SMEM_BYTES>>>(nf, u0, u1, u2, w0, w1, w2,
                                           (float*)d_out, C);
}

// round 4
// speedup vs baseline: 1.5011x; 1.5011x over previous
#include <cuda_runtime.h>
#include <cstdint>
#include <cstddef>

// ---------------- device scratch (module globals: allocation-free) ----------------
#define NODES_MAX 4096
#define SMAX 64
__device__ int g_order[NODES_MAX];
__device__ int g_segStart[SMAX];
__device__ int g_segCount[SMAX];

// ---------------- grouping kernel: counting sort of nodes by species ----------------
__global__ void group_kernel(const int* __restrict__ index, int N) {
    __shared__ int cnt[SMAX];
    __shared__ int cur[SMAX];
    int tid = threadIdx.x;
    if (tid < SMAX) cnt[tid] = 0;
    __syncthreads();
    for (int i = tid; i < N; i += blockDim.x)
        atomicAdd(&cnt[index[i] & (SMAX - 1)], 1);
    __syncthreads();
    if (tid == 0) {
        int run = 0;
        for (int s = 0; s < SMAX; s++) {
            g_segStart[s] = run;
            g_segCount[s] = cnt[s];
            cur[s] = run;
            run += cnt[s];
        }
    }
    __syncthreads();
    for (int i = tid; i < N; i += blockDim.x) {
        int s = index[i] & (SMAX - 1);
        int p = atomicAdd(&cur[s], 1);
        if (p < NODES_MAX) g_order[p] = i;
    }
}

// ---------------- f32x2 helpers ----------------
static __device__ __forceinline__ unsigned long long pk2(float v) {
    unsigned long long r;
    asm("mov.b64 %0, {%1, %1};" : "=l"(r) : "r"(__float_as_uint(v)));
    return r;
}
static __device__ __forceinline__ void fma2(unsigned long long& d,
                                            unsigned long long a,
                                            unsigned long long b) {
    asm("fma.rn.f32x2 %0, %1, %2, %0;" : "+l"(d) : "l"(a), "l"(b));
}
static __device__ __forceinline__ void unpk2(unsigned long long v, float& lo, float& hi) {
    unsigned int a, b;
    asm("mov.b64 {%0, %1}, %2;" : "=r"(a), "=r"(b) : "l"(v));
    lo = __uint_as_float(a);
    hi = __uint_as_float(b);
}

// ---------------- main kernel ----------------
// grid = (C/8, S). 512 threads = 16 warps: warp w -> channel (w>>1), half (w&1).
// Phase 1: uw[c][j][e] in smem, j-plane stride 736 (pad) for LDS.64 alignment.
// Phase 2: groups of 4 nodes; 11 full 64-element tiles (LDS.64 + fma.f32x2),
//          scalar 25-element tail.
#define CT 8
#define JSTR 736
#define CHSTR (9 * JSTR)          // 6624 floats per channel
#define UW_F (CT * CHSTR)         // 52992
#define WS_OFF UW_F
#define SMEM_F (UW_F + 240)
#define SMEM_BYTES (SMEM_F * 4)   // 212,928 B

__global__ __launch_bounds__(512, 1)
void mace_kernel(const float* __restrict__ nf,
                 const float* __restrict__ u0, const float* __restrict__ u1,
                 const float* __restrict__ u2,
                 const float* __restrict__ w0, const float* __restrict__ w1,
                 const float* __restrict__ w2,
                 float* __restrict__ out, int C) {
    extern __shared__ float sm[];
    float* uw = sm;
    float* ws = sm + WS_OFF;

    const int s = blockIdx.y;
    const int m = g_segCount[s];
    if (m == 0) return;             // CTA-uniform, before any barrier
    const int c0 = blockIdx.x * CT;
    const int segBase = g_segStart[s];
    const int tid = threadIdx.x;

    // ---- stage scaled species weights ----
    if (tid < 240) {
        int kg = tid >> 3, c = tid & 7;
        const float* wp; int k; float scale; int mul;
        if (kg < 7)       { wp = w0; k = kg;      scale = 0.61478815f; mul = 7;  }
        else if (kg < 18) { wp = w1; k = kg - 7;  scale = 0.54910049f; mul = 11; }
        else              { wp = w2; k = kg - 18; scale = 0.53728497f; mul = 12; }
        ws[tid] = wp[((size_t)s * mul + k) * C + (c0 + c)] * scale;
    }
    __syncthreads();

    // ---- build uw for all 8 channels ----
    for (int item = tid; item < 6561; item += 512) {
        int j  = item / 729;
        int e  = item - j * 729;
        int ab = e / 9;
        int i  = e - ab * 9;
        const float* up; int mul, koff, il, irr;
        if (i == 0)     { up = u0; mul = 7;  koff = 0;  il = 0;     irr = 1; }
        else if (i < 4) { up = u1; mul = 11; koff = 7;  il = i - 1; irr = 3; }
        else            { up = u2; mul = 12; koff = 18; il = i - 4; irr = 5; }
        const float* ub = up + ((size_t)(ab * 9 + j) * mul) * irr + il;
        float acc[8];
        #pragma unroll
        for (int c = 0; c < 8; c++) acc[c] = 0.f;
        for (int k = 0; k < mul; k++) {
            float uk = __ldg(ub + k * irr);
            const float* wr = ws + (koff + k) * 8;
            #pragma unroll
            for (int c = 0; c < 8; c++) acc[c] += uk * wr[c];
        }
        int off = j * JSTR + e;
        #pragma unroll
        for (int c = 0; c < 8; c++) uw[c * CHSTR + off] = acc[c];
    }
    __syncthreads();

    // ---- main loop ----
    const int lane = tid & 31;
    const int wid  = tid >> 5;          // 0..15
    const int cw   = wid >> 1;          // channel in tile
    const int q    = wid & 1;           // node-group half
    const int crow = c0 + cw;
    const float* uwC = uw + cw * CHSTR;

    const int groups = (m + 3) >> 2;
    for (int g = q; g < groups; g += 2) {
        // gather 36 x-values (4 nodes x 9 j): v0 = elements 0..31, v1 = 32..35
        int n0 = lane / 9, j0 = lane - n0 * 9;
        int idx0 = g * 4 + n0;
        if (idx0 >= m) idx0 = m - 1;
        int nid = g_order[segBase + idx0];
        float v0 = nf[((size_t)nid * C + crow) * 9 + j0];
        float v1 = 0.f;
        if (lane < 4) {
            int idx1 = g * 4 + 3;
            if (idx1 >= m) idx1 = m - 1;
            int nid1 = g_order[segBase + idx1];
            v1 = nf[((size_t)nid1 * C + crow) * 9 + (5 + lane)];
        }

        unsigned long long xx[4][9];
        float* op[4];
        bool valid[4];
        #pragma unroll
        for (int nd = 0; nd < 4; nd++) {
            int n4 = __shfl_sync(0xffffffffu, nid, nd * 9);
            valid[nd] = (g * 4 + nd) < m;
            op[nd] = out + ((size_t)n4 * C + crow) * 729;
            #pragma unroll
            for (int j = 0; j < 9; j++) {
                int el = nd * 9 + j;
                float xv = (el < 32) ? __shfl_sync(0xffffffffu, v0, el)
                                     : __shfl_sync(0xffffffffu, v1, el - 32);
                xx[nd][j] = pk2(xv);
            }
        }

        // 11 full 64-element tiles (elements 0..703)
        #pragma unroll 1
        for (int t = 0; t < 11; t++) {
            int e = t * 64 + lane * 2;
            unsigned long long a0 = 0ull, a1 = 0ull, a2 = 0ull, a3 = 0ull;
            #pragma unroll
            for (int j = 0; j < 9; j++) {
                unsigned long long uv =
                    *reinterpret_cast<const unsigned long long*>(uwC + j * JSTR + e);
                fma2(a0, uv, xx[0][j]);
                fma2(a1, uv, xx[1][j]);
                fma2(a2, uv, xx[2][j]);
                fma2(a3, uv, xx[3][j]);
            }
            float lo, hi;
            if (valid[0]) { unpk2(a0, lo, hi); op[0][e] = lo; op[0][e + 1] = hi; }
            if (valid[1]) { unpk2(a1, lo, hi); op[1][e] = lo; op[1][e + 1] = hi; }
            if (valid[2]) { unpk2(a2, lo, hi); op[2][e] = lo; op[2][e + 1] = hi; }
            if (valid[3]) { unpk2(a3, lo, hi); op[3][e] = lo; op[3][e + 1] = hi; }
        }

        // scalar tail: elements 704..728
        if (lane < 25) {
            int e = 704 + lane;
            float b0 = 0.f, b1 = 0.f, b2 = 0.f, b3 = 0.f;
            #pragma unroll
            for (int j = 0; j < 9; j++) {
                float uv = uwC[j * JSTR + e];
                float l0, h0;
                unpk2(xx[0][j], l0, h0); b0 += uv * l0;
                unpk2(xx[1][j], l0, h0); b1 += uv * l0;
                unpk2(xx[2][j], l0, h0); b2 += uv * l0;
                unpk2(xx[3][j], l0, h0); b3 += uv * l0;
            }
            if (valid[0]) op[0][e] = b0;
            if (valid[1]) op[1][e] = b1;
            if (valid[2]) op[2][e] = b2;
            if (valid[3]) op[3][e] = b3;
        }
    }
}

// ---------------- launch ----------------
extern "C" void kernel_launch(void* const* d_in, const int* in_sizes, int n_in,
                              void* d_out, int out_size) {
    const float *nf = nullptr, *u0 = nullptr, *u1 = nullptr, *u2 = nullptr;
    const float *w0 = nullptr, *w1 = nullptr, *w2 = nullptr;
    const int* index = nullptr;
    int N = 0, nf_sz = 0, w0_sz = 0;
    for (int i = 0; i < n_in; i++) {
        int sz = in_sizes[i];
        switch (sz) {
            case 5103:    u0 = (const float*)d_in[i]; break;
            case 24057:   u1 = (const float*)d_in[i]; break;
            case 43740:   u2 = (const float*)d_in[i]; break;
            case 44800:   w0 = (const float*)d_in[i]; w0_sz = sz; break;
            case 70400:   w1 = (const float*)d_in[i]; break;
            case 76800:   w2 = (const float*)d_in[i]; break;
            case 2048:    index = (const int*)d_in[i]; N = sz; break;
            case 2359296: nf = (const float*)d_in[i]; nf_sz = sz; break;
            default: break;
        }
    }
    if (!nf || !index || !u0 || !u1 || !u2 || !w0 || !w1 || !w2) return;

    const int C = nf_sz / (N * 9);        // 128
    const int S = w0_sz / (7 * C);        // 50

    group_kernel<<<1, 256>>>(index, N);

    cudaFuncSetAttribute(mace_kernel,
                         cudaFuncAttributeMaxDynamicSharedMemorySize, SMEM_BYTES);
    dim3 grid(C / CT, S);
    mace_kernel<<<grid, 512, SMEM_BYTES>>>(nf, u0, u1, u2, w0, w1, w2,
                                           (float*)d_out, C);
}

// round 5
// speedup vs baseline: 1.5396x; 1.0257x over previous
#include <cuda_runtime.h>
#include <cstdint>
#include <cstddef>

// ---------------- device scratch (module globals: allocation-free) ----------------
#define NODES_MAX 4096
#define SMAX 64
__device__ int g_order[NODES_MAX];
__device__ int g_segStart[SMAX];
__device__ int g_segCount[SMAX];

// ---------------- grouping kernel: counting sort of nodes by species ----------------
__global__ void group_kernel(const int* __restrict__ index, int N) {
    __shared__ int cnt[SMAX];
    __shared__ int cur[SMAX];
    int tid = threadIdx.x;
    if (tid < SMAX) cnt[tid] = 0;
    __syncthreads();
    for (int i = tid; i < N; i += blockDim.x)
        atomicAdd(&cnt[index[i] & (SMAX - 1)], 1);
    __syncthreads();
    if (tid == 0) {
        int run = 0;
        for (int s = 0; s < SMAX; s++) {
            g_segStart[s] = run;
            g_segCount[s] = cnt[s];
            cur[s] = run;
            run += cnt[s];
        }
    }
    __syncthreads();
    for (int i = tid; i < N; i += blockDim.x) {
        int s = index[i] & (SMAX - 1);
        int p = atomicAdd(&cur[s], 1);
        if (p < NODES_MAX) g_order[p] = i;
    }
}

// ---------------- f32x2 helpers ----------------
typedef unsigned long long ull;
static __device__ __forceinline__ ull pk2(float v) {        // (v, v)
    ull r;
    asm("mov.b64 %0, {%1, %1};" : "=l"(r) : "r"(__float_as_uint(v)));
    return r;
}
static __device__ __forceinline__ ull pkab(float a, float b) {  // (a, b)
    ull r;
    asm("mov.b64 %0, {%1, %2};" : "=l"(r) : "r"(__float_as_uint(a)), "r"(__float_as_uint(b)));
    return r;
}
static __device__ __forceinline__ void fma2(ull& d, ull a, ull b) {
    asm("fma.rn.f32x2 %0, %1, %2, %0;" : "+l"(d) : "l"(a), "l"(b));
}
static __device__ __forceinline__ void unpk2(ull v, float& lo, float& hi) {
    unsigned int a, b;
    asm("mov.b64 {%0, %1}, %2;" : "=r"(a), "=r"(b) : "l"(v));
    lo = __uint_as_float(a);
    hi = __uint_as_float(b);
}

// ---------------- main kernel ----------------
// grid = (C/8, S), 1024 threads = 32 warps: warp -> channel (wid>>2), quarter (wid&3).
// Phase 1: uw[c][j][e] (e = ab*9+i, 729) in smem, plain stride 729.
// Phase 2: 4 nodes per group; f32x2 lanes carry (node0,node1)/(node2,node3);
//          uw loaded scalar LDS.32 + dup-pack; stores are 128B-coalesced STG.32.
#define CT 8
#define CHSTR 6561
#define UW_F (CT * CHSTR)          // 52488
#define WS_OFF UW_F
#define SMEM_BYTES ((UW_F + 240) * 4)   // 210,912 B

__global__ __launch_bounds__(1024, 1)
void mace_kernel(const float* __restrict__ nf,
                 const float* __restrict__ u0, const float* __restrict__ u1,
                 const float* __restrict__ u2,
                 const float* __restrict__ w0, const float* __restrict__ w1,
                 const float* __restrict__ w2,
                 float* __restrict__ out, int C) {
    extern __shared__ float sm[];
    float* uw = sm;
    float* ws = sm + WS_OFF;

    const int s = blockIdx.y;
    const int m = g_segCount[s];
    if (m == 0) return;             // CTA-uniform, before any barrier
    const int c0 = blockIdx.x * CT;
    const int segBase = g_segStart[s];
    const int tid = threadIdx.x;

    // ---- stage scaled species weights: ws[kglobal][c] ----
    if (tid < 240) {
        int kg = tid >> 3, c = tid & 7;
        const float* wp; int k; float scale; int mul;
        if (kg < 7)       { wp = w0; k = kg;      scale = 0.61478815f; mul = 7;  }
        else if (kg < 18) { wp = w1; k = kg - 7;  scale = 0.54910049f; mul = 11; }
        else              { wp = w2; k = kg - 18; scale = 0.53728497f; mul = 12; }
        ws[tid] = wp[((size_t)s * mul + k) * C + (c0 + c)] * scale;
    }
    __syncthreads();

    // ---- build uw for all 8 channels: item = j*729 + e ----
    for (int item = tid; item < 6561; item += 1024) {
        int j  = item / 729;
        int e  = item - j * 729;
        int ab = e / 9;
        int i  = e - ab * 9;
        const float* up; int mul, koff, il, irr;
        if (i == 0)     { up = u0; mul = 7;  koff = 0;  il = 0;     irr = 1; }
        else if (i < 4) { up = u1; mul = 11; koff = 7;  il = i - 1; irr = 3; }
        else            { up = u2; mul = 12; koff = 18; il = i - 4; irr = 5; }
        const float* ub = up + ((size_t)(ab * 9 + j) * mul) * irr + il;
        float acc[8];
        #pragma unroll
        for (int c = 0; c < 8; c++) acc[c] = 0.f;
        for (int k = 0; k < mul; k++) {
            float uk = __ldg(ub + k * irr);
            const float* wr = ws + (koff + k) * 8;
            #pragma unroll
            for (int c = 0; c < 8; c++) acc[c] += uk * wr[c];
        }
        #pragma unroll
        for (int c = 0; c < 8; c++) uw[c * CHSTR + item] = acc[c];
    }
    __syncthreads();

    // ---- main loop ----
    const int lane = tid & 31;
    const int wid  = tid >> 5;          // 0..31
    const int cw   = wid >> 2;          // channel in tile
    const int q    = wid & 3;           // node-group quarter
    const int crow = c0 + cw;
    const float* uwC = uw + cw * CHSTR;

    const int groups = (m + 3) >> 2;
    for (int g = q; g < groups; g += 4) {
        // gather 36 x-values (4 nodes x 9 j): v0 = elements 0..31, v1 = 32..35
        int n0 = lane / 9, j0 = lane - n0 * 9;
        int idx0 = g * 4 + n0;
        if (idx0 >= m) idx0 = m - 1;               // clamp: safe read, store guarded
        int nid = g_order[segBase + idx0];
        float v0 = nf[((size_t)nid * C + crow) * 9 + j0];
        float v1 = 0.f;
        if (lane < 4) {
            int idx1 = g * 4 + 3;
            if (idx1 >= m) idx1 = m - 1;
            v1 = nf[((size_t)g_order[segBase + idx1] * C + crow) * 9 + (5 + lane)];
        }

        // output row offsets (32-bit: max index 191M < 2^31)
        unsigned o[4];
        bool valid[4];
        #pragma unroll
        for (int nd = 0; nd < 4; nd++) {
            int n4 = __shfl_sync(0xffffffffu, nid, nd * 9);
            valid[nd] = (g * 4 + nd) < m;
            o[nd] = (unsigned)(n4 * C + crow) * 729u;
        }

        // pack x as node-pairs: x01[j] = (x[n0][j], x[n1][j]), x23 likewise
        ull x01[9], x23[9];
        #pragma unroll
        for (int j = 0; j < 9; j++) {
            float a = __shfl_sync(0xffffffffu, v0, j);
            float b = __shfl_sync(0xffffffffu, v0, 9 + j);
            x01[j] = pkab(a, b);
            float c2 = __shfl_sync(0xffffffffu, v0, 18 + j);
            int el3 = 27 + j;
            float d = (el3 < 32) ? __shfl_sync(0xffffffffu, v0, el3)
                                 : __shfl_sync(0xffffffffu, v1, el3 - 32);
            x23[j] = pkab(c2, d);
        }

        // 22 full 32-element tiles: lane = element; acc pairs = (n0,n1),(n2,n3)
        #pragma unroll 1
        for (int t = 0; t < 22; t++) {
            int e = t * 32 + lane;
            ull a01 = 0ull, a23 = 0ull;
            #pragma unroll
            for (int j = 0; j < 9; j++) {
                ull up = pk2(uwC[j * 729 + e]);
                fma2(a01, up, x01[j]);
                fma2(a23, up, x23[j]);
            }
            float r0, r1, r2, r3;
            unpk2(a01, r0, r1);
            unpk2(a23, r2, r3);
            if (valid[0]) out[o[0] + e] = r0;
            if (valid[1]) out[o[1] + e] = r1;
            if (valid[2]) out[o[2] + e] = r2;
            if (valid[3]) out[o[3] + e] = r3;
        }
        // tail: elements 704..728 (25)
        if (lane < 25) {
            int e = 704 + lane;
            ull a01 = 0ull, a23 = 0ull;
            #pragma unroll
            for (int j = 0; j < 9; j++) {
                ull up = pk2(uwC[j * 729 + e]);
                fma2(a01, up, x01[j]);
                fma2(a23, up, x23[j]);
            }
            float r0, r1, r2, r3;
            unpk2(a01, r0, r1);
            unpk2(a23, r2, r3);
            if (valid[0]) out[o[0] + e] = r0;
            if (valid[1]) out[o[1] + e] = r1;
            if (valid[2]) out[o[2] + e] = r2;
            if (valid[3]) out[o[3] + e] = r3;
        }
    }
}

// ---------------- launch ----------------
extern "C" void kernel_launch(void* const* d_in, const int* in_sizes, int n_in,
                              void* d_out, int out_size) {
    const float *nf = nullptr, *u0 = nullptr, *u1 = nullptr, *u2 = nullptr;
    const float *w0 = nullptr, *w1 = nullptr, *w2 = nullptr;
    const int* index = nullptr;
    int N = 0, nf_sz = 0, w0_sz = 0;
    for (int i = 0; i < n_in; i++) {
        int sz = in_sizes[i];
        switch (sz) {
            case 5103:    u0 = (const float*)d_in[i]; break;
            case 24057:   u1 = (const float*)d_in[i]; break;
            case 43740:   u2 = (const float*)d_in[i]; break;
            case 44800:   w0 = (const float*)d_in[i]; w0_sz = sz; break;
            case 70400:   w1 = (const float*)d_in[i]; break;
            case 76800:   w2 = (const float*)d_in[i]; break;
            case 2048:    index = (const int*)d_in[i]; N = sz; break;
            case 2359296: nf = (const float*)d_in[i]; nf_sz = sz; break;
            default: break;
        }
    }
    if (!nf || !index || !u0 || !u1 || !u2 || !w0 || !w1 || !w2) return;

    const int C = nf_sz / (N * 9);        // 128
    const int S = w0_sz / (7 * C);        // 50

    group_kernel<<<1, 256>>>(index, N);

    cudaFuncSetAttribute(mace_kernel,
                         cudaFuncAttributeMaxDynamicSharedMemorySize, SMEM_BYTES);
    dim3 grid(C / CT, S);
    mace_kernel<<<grid, 1024, SMEM_BYTES>>>(nf, u0, u1, u2, w0, w1, w2,
                                            (float*)d_out, C);
}

// round 6
// speedup vs baseline: 1.8723x; 1.2161x over previous
#include <cuda_runtime.h>
#include <cstdint>
#include <cstddef>

// ---------------- device scratch (module globals: allocation-free) ----------------
#define NODES_MAX 4096
#define SMAX 64
__device__ int g_order[NODES_MAX];
__device__ int g_segStart[SMAX];
__device__ int g_segCount[SMAX];

// ---------------- grouping kernel: counting sort of nodes by species ----------------
__global__ void group_kernel(const int* __restrict__ index, int N) {
    __shared__ int cnt[SMAX];
    __shared__ int cur[SMAX];
    int tid = threadIdx.x;
    if (tid < SMAX) cnt[tid] = 0;
    __syncthreads();
    for (int i = tid; i < N; i += blockDim.x)
        atomicAdd(&cnt[index[i] & (SMAX - 1)], 1);
    __syncthreads();
    if (tid == 0) {
        int run = 0;
        for (int s = 0; s < SMAX; s++) {
            g_segStart[s] = run;
            g_segCount[s] = cnt[s];
            cur[s] = run;
            run += cnt[s];
        }
    }
    __syncthreads();
    for (int i = tid; i < N; i += blockDim.x) {
        int s = index[i] & (SMAX - 1);
        int p = atomicAdd(&cur[s], 1);
        if (p < NODES_MAX) g_order[p] = i;
    }
}

// ---------------- f32x2 helpers ----------------
typedef unsigned long long ull;
static __device__ __forceinline__ ull pk2(float v) {        // (v, v)
    ull r;
    asm("mov.b64 %0, {%1, %1};" : "=l"(r) : "r"(__float_as_uint(v)));
    return r;
}
static __device__ __forceinline__ ull pkab(float a, float b) {  // (a, b)
    ull r;
    asm("mov.b64 %0, {%1, %2};" : "=l"(r) : "r"(__float_as_uint(a)), "r"(__float_as_uint(b)));
    return r;
}
static __device__ __forceinline__ void fma2(ull& d, ull a, ull b) {
    asm("fma.rn.f32x2 %0, %1, %2, %0;" : "+l"(d) : "l"(a), "l"(b));
}
static __device__ __forceinline__ void unpk2(ull v, float& lo, float& hi) {
    unsigned int a, b;
    asm("mov.b64 {%0, %1}, %2;" : "=r"(a), "=r"(b) : "l"(v));
    lo = __uint_as_float(a);
    hi = __uint_as_float(b);
}

#define CT 8
#define CHSTR 6561
#define UW_F (CT * CHSTR)          // 52488
#define WS_OFF UW_F
#define SMEM_BYTES ((UW_F + 240) * 4)   // 210,912 B

// ---------------- build helper: compile-time chunk params -> unrolled, batched LDG ----
template<int MUL, int IRR, int KOFF, int IBASE>
static __device__ __forceinline__ void build_chunk(const float* __restrict__ up,
                                                   const float* __restrict__ ws,
                                                   float* __restrict__ uw, int tid) {
    for (int idx = tid; idx < 729 * IRR; idx += 1024) {
        int ab  = idx / (9 * IRR);
        int rem = idx - ab * 9 * IRR;
        int j   = rem / IRR;
        int il  = rem - j * IRR;
        const float* ub = up + ((ab * 9 + j) * MUL) * IRR + il;
        float uv[MUL];
        #pragma unroll
        for (int k = 0; k < MUL; k++) uv[k] = __ldg(ub + k * IRR);
        float acc[8];
        #pragma unroll
        for (int c = 0; c < 8; c++) acc[c] = 0.f;
        #pragma unroll
        for (int k = 0; k < MUL; k++) {
            const float* wr = ws + (KOFF + k) * 8;
            #pragma unroll
            for (int c = 0; c < 8; c++) acc[c] += uv[k] * wr[c];
        }
        int off = j * 729 + ab * 9 + IBASE + il;
        #pragma unroll
        for (int c = 0; c < 8; c++) uw[c * CHSTR + off] = acc[c];
    }
}

// ---------------- main kernel ----------------
// grid = (C/8, S), 1024 threads = 32 warps: warp -> channel (wid>>2), quarter (wid&3).
// Mainloop: 4 nodes/group as f32x2 node-pairs; 64-element tiles with two
// element-accumulators (e, e+32) -> 4 independent fma2 chains; streaming stores.
__global__ __launch_bounds__(1024, 1)
void mace_kernel(const float* __restrict__ nf,
                 const float* __restrict__ u0, const float* __restrict__ u1,
                 const float* __restrict__ u2,
                 const float* __restrict__ w0, const float* __restrict__ w1,
                 const float* __restrict__ w2,
                 float* __restrict__ out, int C) {
    extern __shared__ float sm[];
    float* uw = sm;
    float* ws = sm + WS_OFF;

    const int s = blockIdx.y;
    const int m = g_segCount[s];
    if (m == 0) return;             // CTA-uniform, before any barrier
    const int c0 = blockIdx.x * CT;
    const int segBase = g_segStart[s];
    const int tid = threadIdx.x;

    // ---- stage scaled species weights: ws[kglobal][c] ----
    if (tid < 240) {
        int kg = tid >> 3, c = tid & 7;
        const float* wp; int k; float scale; int mul;
        if (kg < 7)       { wp = w0; k = kg;      scale = 0.61478815f; mul = 7;  }
        else if (kg < 18) { wp = w1; k = kg - 7;  scale = 0.54910049f; mul = 11; }
        else              { wp = w2; k = kg - 18; scale = 0.53728497f; mul = 12; }
        ws[tid] = wp[((size_t)s * mul + k) * C + (c0 + c)] * scale;
    }
    __syncthreads();

    // ---- build uw: three compile-time chunks (full unroll, batched LDG) ----
    build_chunk<7, 1, 0, 0>(u0, ws, uw, tid);
    build_chunk<11, 3, 7, 1>(u1, ws, uw, tid);
    build_chunk<12, 5, 18, 4>(u2, ws, uw, tid);
    __syncthreads();

    // ---- main loop ----
    const int lane = tid & 31;
    const int wid  = tid >> 5;          // 0..31
    const int cw   = wid >> 2;          // channel in tile
    const int q    = wid & 3;           // node-group quarter
    const int crow = c0 + cw;
    const float* uwC = uw + cw * CHSTR;

    const int groups = (m + 3) >> 2;
    for (int g = q; g < groups; g += 4) {
        // gather 36 x-values (4 nodes x 9 j): v0 = elements 0..31, v1 = 32..35
        int n0 = lane / 9, j0 = lane - n0 * 9;
        int idx0 = g * 4 + n0;
        if (idx0 >= m) idx0 = m - 1;               // clamp: safe read, store guarded
        int nid = g_order[segBase + idx0];
        float v0 = nf[((size_t)nid * C + crow) * 9 + j0];
        float v1 = 0.f;
        if (lane < 4) {
            int idx1 = g * 4 + 3;
            if (idx1 >= m) idx1 = m - 1;
            v1 = nf[((size_t)g_order[segBase + idx1] * C + crow) * 9 + (5 + lane)];
        }

        unsigned o[4];
        bool valid[4];
        #pragma unroll
        for (int nd = 0; nd < 4; nd++) {
            int n4 = __shfl_sync(0xffffffffu, nid, nd * 9);
            valid[nd] = (g * 4 + nd) < m;
            o[nd] = (unsigned)(n4 * C + crow) * 729u;
        }

        // pack x as node-pairs
        ull x01[9], x23[9];
        #pragma unroll
        for (int j = 0; j < 9; j++) {
            float a = __shfl_sync(0xffffffffu, v0, j);
            float b = __shfl_sync(0xffffffffu, v0, 9 + j);
            x01[j] = pkab(a, b);
            float c2 = __shfl_sync(0xffffffffu, v0, 18 + j);
            int el3 = 27 + j;
            float d = (el3 < 32) ? __shfl_sync(0xffffffffu, v0, el3)
                                 : __shfl_sync(0xffffffffu, v1, el3 - 32);
            x23[j] = pkab(c2, d);
        }

        // 11 tiles of 64 elements: two element-accs (e, e+32) x two node-pairs
        #pragma unroll 1
        for (int t = 0; t < 11; t++) {
            int e = t * 64 + lane;
            ull aA = 0ull, bA = 0ull, aB = 0ull, bB = 0ull;
            #pragma unroll
            for (int j = 0; j < 9; j++) {
                float uA = uwC[j * 729 + e];
                float uB = uwC[j * 729 + e + 32];
                ull dA = pk2(uA);
                ull dB = pk2(uB);
                fma2(aA, dA, x01[j]);
                fma2(bA, dA, x23[j]);
                fma2(aB, dB, x01[j]);
                fma2(bB, dB, x23[j]);
            }
            float r0, r1, r2, r3, s0, s1, s2, s3;
            unpk2(aA, r0, r1); unpk2(bA, r2, r3);
            unpk2(aB, s0, s1); unpk2(bB, s2, s3);
            if (valid[0]) { __stcs(out + o[0] + e, r0); __stcs(out + o[0] + e + 32, s0); }
            if (valid[1]) { __stcs(out + o[1] + e, r1); __stcs(out + o[1] + e + 32, s1); }
            if (valid[2]) { __stcs(out + o[2] + e, r2); __stcs(out + o[2] + e + 32, s2); }
            if (valid[3]) { __stcs(out + o[3] + e, r3); __stcs(out + o[3] + e + 32, s3); }
        }
        // tail: elements 704..728 (25)
        if (lane < 25) {
            int e = 704 + lane;
            ull a01 = 0ull, a23 = 0ull;
            #pragma unroll
            for (int j = 0; j < 9; j++) {
                ull up = pk2(uwC[j * 729 + e]);
                fma2(a01, up, x01[j]);
                fma2(a23, up, x23[j]);
            }
            float r0, r1, r2, r3;
            unpk2(a01, r0, r1);
            unpk2(a23, r2, r3);
            if (valid[0]) __stcs(out + o[0] + e, r0);
            if (valid[1]) __stcs(out + o[1] + e, r1);
            if (valid[2]) __stcs(out + o[2] + e, r2);
            if (valid[3]) __stcs(out + o[3] + e, r3);
        }
    }
}

// ---------------- launch ----------------
extern "C" void kernel_launch(void* const* d_in, const int* in_sizes, int n_in,
                              void* d_out, int out_size) {
    const float *nf = nullptr, *u0 = nullptr, *u1 = nullptr, *u2 = nullptr;
    const float *w0 = nullptr, *w1 = nullptr, *w2 = nullptr;
    const int* index = nullptr;
    int N = 0, nf_sz = 0, w0_sz = 0;
    for (int i = 0; i < n_in; i++) {
        int sz = in_sizes[i];
        switch (sz) {
            case 5103:    u0 = (const float*)d_in[i]; break;
            case 24057:   u1 = (const float*)d_in[i]; break;
            case 43740:   u2 = (const float*)d_in[i]; break;
            case 44800:   w0 = (const float*)d_in[i]; w0_sz = sz; break;
            case 70400:   w1 = (const float*)d_in[i]; break;
            case 76800:   w2 = (const float*)d_in[i]; break;
            case 2048:    index = (const int*)d_in[i]; N = sz; break;
            case 2359296: nf = (const float*)d_in[i]; nf_sz = sz; break;
            default: break;
        }
    }
    if (!nf || !index || !u0 || !u1 || !u2 || !w0 || !w1 || !w2) return;

    const int C = nf_sz / (N * 9);        // 128
    const int S = w0_sz / (7 * C);        // 50

    group_kernel<<<1, 256>>>(index, N);

    cudaFuncSetAttribute(mace_kernel,
                         cudaFuncAttributeMaxDynamicSharedMemorySize, SMEM_BYTES);
    dim3 grid(C / CT, S);
    mace_kernel<<<grid, 1024, SMEM_BYTES>>>(nf, u0, u1, u2, w0, w1, w2,
                                            (float*)d_out, C);
}

// round 7
// speedup vs baseline: 1.8749x; 1.0014x over previous
#include <cuda_runtime.h>
#include <cstdint>
#include <cstddef>

// ---------------- device scratch (module globals: allocation-free) ----------------
#define NODES_MAX 4096
#define SMAX 64
__device__ int g_order[NODES_MAX];
__device__ int g_segStart[SMAX];
__device__ int g_segCount[SMAX];

// ---------------- grouping kernel: counting sort of nodes by species ----------------
__global__ void group_kernel(const int* __restrict__ index, int N) {
    __shared__ int cnt[SMAX];
    __shared__ int cur[SMAX];
    int tid = threadIdx.x;
    if (tid < SMAX) cnt[tid] = 0;
    __syncthreads();
    for (int i = tid; i < N; i += blockDim.x)
        atomicAdd(&cnt[index[i] & (SMAX - 1)], 1);
    __syncthreads();
    if (tid == 0) {
        int run = 0;
        for (int s = 0; s < SMAX; s++) {
            g_segStart[s] = run;
            g_segCount[s] = cnt[s];
            cur[s] = run;
            run += cnt[s];
        }
    }
    __syncthreads();
    for (int i = tid; i < N; i += blockDim.x) {
        int s = index[i] & (SMAX - 1);
        int p = atomicAdd(&cur[s], 1);
        if (p < NODES_MAX) g_order[p] = i;
    }
}

// ---------------- f32x2 helpers ----------------
typedef unsigned long long ull;
static __device__ __forceinline__ ull pk2(float v) {        // (v, v)
    ull r;
    asm("mov.b64 %0, {%1, %1};" : "=l"(r) : "r"(__float_as_uint(v)));
    return r;
}
static __device__ __forceinline__ ull pkab(float a, float b) {  // (a, b)
    ull r;
    asm("mov.b64 %0, {%1, %2};" : "=l"(r) : "r"(__float_as_uint(a)), "r"(__float_as_uint(b)));
    return r;
}
static __device__ __forceinline__ void fma2(ull& d, ull a, ull b) {
    asm("fma.rn.f32x2 %0, %1, %2, %0;" : "+l"(d) : "l"(a), "l"(b));
}
static __device__ __forceinline__ void unpk2(ull v, float& lo, float& hi) {
    unsigned int a, b;
    asm("mov.b64 {%0, %1}, %2;" : "=r"(a), "=r"(b) : "l"(v));
    lo = __uint_as_float(a);
    hi = __uint_as_float(b);
}

#define CT 8
#define CHSTR 6561
#define UW_F (CT * CHSTR)          // 52488
#define WS_OFF UW_F
#define SMEM_BYTES ((UW_F + 240) * 4)   // 210,912 B

// ---------------- build helper: compile-time chunk params -> unrolled, batched LDG ----
template<int MUL, int IRR, int KOFF, int IBASE>
static __device__ __forceinline__ void build_chunk(const float* __restrict__ up,
                                                   const float* __restrict__ ws,
                                                   float* __restrict__ uw, int tid) {
    for (int idx = tid; idx < 729 * IRR; idx += 512) {
        int ab  = idx / (9 * IRR);
        int rem = idx - ab * 9 * IRR;
        int j   = rem / IRR;
        int il  = rem - j * IRR;
        const float* ub = up + ((ab * 9 + j) * MUL) * IRR + il;
        float uv[MUL];
        #pragma unroll
        for (int k = 0; k < MUL; k++) uv[k] = __ldg(ub + k * IRR);
        float acc[8];
        #pragma unroll
        for (int c = 0; c < 8; c++) acc[c] = 0.f;
        #pragma unroll
        for (int k = 0; k < MUL; k++) {
            const float* wr = ws + (KOFF + k) * 8;
            #pragma unroll
            for (int c = 0; c < 8; c++) acc[c] += uv[k] * wr[c];
        }
        int off = j * 729 + ab * 9 + IBASE + il;
        #pragma unroll
        for (int c = 0; c < 8; c++) uw[c * CHSTR + off] = acc[c];
    }
}

// ---------------- main kernel ----------------
// grid = (C/8, S), 512 threads = 16 warps: warp -> channel (wid>>1), half (wid&1).
// 8 nodes per group (4 f32x2 node-pairs): per 32-elem tile only 9 LDS + 8 STG
// L1 ops for 256 outputs. x gathered via 3 lanesets of warp shfl.
__global__ __launch_bounds__(512, 1)
void mace_kernel(const float* __restrict__ nf,
                 const float* __restrict__ u0, const float* __restrict__ u1,
                 const float* __restrict__ u2,
                 const float* __restrict__ w0, const float* __restrict__ w1,
                 const float* __restrict__ w2,
                 float* __restrict__ out, int C) {
    extern __shared__ float sm[];
    float* uw = sm;
    float* ws = sm + WS_OFF;

    const int s = blockIdx.y;
    const int m = g_segCount[s];
    if (m == 0) return;             // CTA-uniform, before any barrier
    const int c0 = blockIdx.x * CT;
    const int segBase = g_segStart[s];
    const int tid = threadIdx.x;

    // ---- stage scaled species weights: ws[kglobal][c] ----
    if (tid < 240) {
        int kg = tid >> 3, c = tid & 7;
        const float* wp; int k; float scale; int mul;
        if (kg < 7)       { wp = w0; k = kg;      scale = 0.61478815f; mul = 7;  }
        else if (kg < 18) { wp = w1; k = kg - 7;  scale = 0.54910049f; mul = 11; }
        else              { wp = w2; k = kg - 18; scale = 0.53728497f; mul = 12; }
        ws[tid] = wp[((size_t)s * mul + k) * C + (c0 + c)] * scale;
    }
    __syncthreads();

    // ---- build uw: three compile-time chunks (full unroll, batched LDG) ----
    build_chunk<7, 1, 0, 0>(u0, ws, uw, tid);
    build_chunk<11, 3, 7, 1>(u1, ws, uw, tid);
    build_chunk<12, 5, 18, 4>(u2, ws, uw, tid);
    __syncthreads();

    // ---- main loop: 8 nodes per group ----
    const int lane = tid & 31;
    const int wid  = tid >> 5;          // 0..15
    const int cw   = wid >> 1;          // channel in tile
    const int q    = wid & 1;           // node-group half
    const int crow = c0 + cw;
    const float* uwC = uw + cw * CHSTR;

    const int groups = (m + 7) >> 3;
    for (int g = q; g < groups; g += 2) {
        // gather 72 x-values (8 nodes x 9 j) in 3 lanesets:
        //   v0: el 0..31, v1: el 32..63, v2: el 64..71 (lanes 0..7)
        int n0 = lane / 9, j0 = lane - n0 * 9;           // el = lane
        int idx0 = g * 8 + n0;
        if (idx0 >= m) idx0 = m - 1;                     // clamp: safe read, store masked
        int nid0 = g_order[segBase + idx0];
        float v0 = nf[((size_t)nid0 * C + crow) * 9 + j0];

        int el1 = 32 + lane;
        int n1 = el1 / 9, j1 = el1 - n1 * 9;             // nd 3..7
        int idx1 = g * 8 + n1;
        if (idx1 >= m) idx1 = m - 1;
        int nid1 = g_order[segBase + idx1];
        float v1 = nf[((size_t)nid1 * C + crow) * 9 + j1];

        float v2 = 0.f;
        if (lane < 8) {                                   // el 64..71 -> nd 7, j = 1+lane
            int idx2 = g * 8 + 7;
            if (idx2 >= m) idx2 = m - 1;
            v2 = nf[((size_t)g_order[segBase + idx2] * C + crow) * 9 + (1 + lane)];
        }

        // node ids: 0..3 from v0 laneset (lanes 0,9,18,27); 4..7 from v1 (4,13,22,31)
        unsigned o[8];
        bool valid[8];
        #pragma unroll
        for (int nd = 0; nd < 8; nd++) {
            int src = (nd < 4) ? nd * 9 : (nd * 9 - 32);
            int nn = (nd < 4) ? __shfl_sync(0xffffffffu, nid0, src)
                              : __shfl_sync(0xffffffffu, nid1, src);
            valid[nd] = (g * 8 + nd) < m;
            o[nd] = (unsigned)(nn * C + crow) * 729u;
        }

        // pack x node-pairs: xp[p][j] = (x[2p][j], x[2p+1][j]); el a=18p+j, b=18p+9+j
        ull xp[4][9];
        #pragma unroll
        for (int j = 0; j < 9; j++) {
            #pragma unroll
            for (int p = 0; p < 4; p++) {
                int ea = 18 * p + j, eb = 18 * p + 9 + j;
                float a = (ea < 32) ? __shfl_sync(0xffffffffu, v0, ea)
                         : (ea < 64) ? __shfl_sync(0xffffffffu, v1, ea - 32)
                                     : __shfl_sync(0xffffffffu, v2, ea - 64);
                float b = (eb < 32) ? __shfl_sync(0xffffffffu, v0, eb)
                         : (eb < 64) ? __shfl_sync(0xffffffffu, v1, eb - 32)
                                     : __shfl_sync(0xffffffffu, v2, eb - 64);
                xp[p][j] = pkab(a, b);
            }
        }

        // 22 full 32-element tiles + 25-element tail
        #pragma unroll 1
        for (int t = 0; t < 23; t++) {
            int e = t * 32 + lane;
            bool act = (t < 22) | (lane < 25);
            int ee = act ? e : 728;
            ull a0 = 0ull, a1 = 0ull, a2 = 0ull, a3 = 0ull;
            #pragma unroll
            for (int j = 0; j < 9; j++) {
                ull up = pk2(uwC[j * 729 + ee]);
                fma2(a0, up, xp[0][j]);
                fma2(a1, up, xp[1][j]);
                fma2(a2, up, xp[2][j]);
                fma2(a3, up, xp[3][j]);
            }
            float r0, r1, r2, r3, r4, r5, r6, r7;
            unpk2(a0, r0, r1); unpk2(a1, r2, r3);
            unpk2(a2, r4, r5); unpk2(a3, r6, r7);
            if (act) {
                if (valid[0]) __stcs(out + o[0] + e, r0);
                if (valid[1]) __stcs(out + o[1] + e, r1);
                if (valid[2]) __stcs(out + o[2] + e, r2);
                if (valid[3]) __stcs(out + o[3] + e, r3);
                if (valid[4]) __stcs(out + o[4] + e, r4);
                if (valid[5]) __stcs(out + o[5] + e, r5);
                if (valid[6]) __stcs(out + o[6] + e, r6);
                if (valid[7]) __stcs(out + o[7] + e, r7);
            }
        }
    }
}

// ---------------- launch ----------------
extern "C" void kernel_launch(void* const* d_in, const int* in_sizes, int n_in,
                              void* d_out, int out_size) {
    const float *nf = nullptr, *u0 = nullptr, *u1 = nullptr, *u2 = nullptr;
    const float *w0 = nullptr, *w1 = nullptr, *w2 = nullptr;
    const int* index = nullptr;
    int N = 0, nf_sz = 0, w0_sz = 0;
    for (int i = 0; i < n_in; i++) {
        int sz = in_sizes[i];
        switch (sz) {
            case 5103:    u0 = (const float*)d_in[i]; break;
            case 24057:   u1 = (const float*)d_in[i]; break;
            case 43740:   u2 = (const float*)d_in[i]; break;
            case 44800:   w0 = (const float*)d_in[i]; w0_sz = sz; break;
            case 70400:   w1 = (const float*)d_in[i]; break;
            case 76800:   w2 = (const float*)d_in[i]; break;
            case 2048:    index = (const int*)d_in[i]; N = sz; break;
            case 2359296: nf = (const float*)d_in[i]; nf_sz = sz; break;
            default: break;
        }
    }
    if (!nf || !index || !u0 || !u1 || !u2 || !w0 || !w1 || !w2) return;

    const int C = nf_sz / (N * 9);        // 128
    const int S = w0_sz / (7 * C);        // 50

    group_kernel<<<1, 256>>>(index, N);

    cudaFuncSetAttribute(mace_kernel,
                         cudaFuncAttributeMaxDynamicSharedMemorySize, SMEM_BYTES);
    dim3 grid(C / CT, S);
    mace_kernel<<<grid, 512, SMEM_BYTES>>>(nf, u0, u1, u2, w0, w1, w2,
                                           (float*)d_out, C);
}

// round 8
// speedup vs baseline: 2.2938x; 1.2234x over previous
#include <cuda_runtime.h>
#include <cstdint>
#include <cstddef>

// ---------------- device scratch (module globals: allocation-free) ----------------
#define NODES_MAX 4096
#define SMAX 64
__device__ int g_order[NODES_MAX];
__device__ int g_segStart[SMAX];
__device__ int g_segCount[SMAX];

// ---------------- grouping kernel: counting sort of nodes by species ----------------
__global__ void group_kernel(const int* __restrict__ index, int N) {
    __shared__ int cnt[SMAX];
    __shared__ int cur[SMAX];
    int tid = threadIdx.x;
    if (tid < SMAX) cnt[tid] = 0;
    __syncthreads();
    for (int i = tid; i < N; i += blockDim.x)
        atomicAdd(&cnt[index[i] & (SMAX - 1)], 1);
    __syncthreads();
    if (tid == 0) {
        int run = 0;
        for (int s = 0; s < SMAX; s++) {
            g_segStart[s] = run;
            g_segCount[s] = cnt[s];
            cur[s] = run;
            run += cnt[s];
        }
    }
    __syncthreads();
    for (int i = tid; i < N; i += blockDim.x) {
        int s = index[i] & (SMAX - 1);
        int p = atomicAdd(&cur[s], 1);
        if (p < NODES_MAX) g_order[p] = i;
    }
}

// ---------------- f32x2 helpers ----------------
typedef unsigned long long ull;
static __device__ __forceinline__ ull pk2(float v) {        // (v, v)
    ull r;
    asm("mov.b64 %0, {%1, %1};" : "=l"(r) : "r"(__float_as_uint(v)));
    return r;
}
static __device__ __forceinline__ void fma2(ull& d, ull a, ull b) {
    asm("fma.rn.f32x2 %0, %1, %2, %0;" : "+l"(d) : "l"(a), "l"(b));
}
static __device__ __forceinline__ void unpk2(ull v, float& lo, float& hi) {
    unsigned int a, b;
    asm("mov.b64 {%0, %1}, %2;" : "=r"(a), "=r"(b) : "l"(v));
    lo = __uint_as_float(a);
    hi = __uint_as_float(b);
}
static __device__ __forceinline__ float lo2(ull v) {
    unsigned int a, b;
    asm("mov.b64 {%0, %1}, %2;" : "=r"(a), "=r"(b) : "l"(v));
    return __uint_as_float(a);
}

// ---------------- layout ----------------
// Per channel c the output row base o=(n*128+c)*729 satisfies o mod 4 == c mod 4.
// Phase h(c) = (-c) mod 4: quads cover elements [h, h+4*Kq), head/tail scalar.
// uw smem stores element e of channel c at j*JSTR + (e - h)  (head wrapped to end),
// so quad LDS.128 at j*JSTR + 4*q is 16B-aligned.
#define CT 8
#define JSTR 732
#define CHSTR (9 * JSTR)               // 6588
#define UW_F (CT * CHSTR)              // 52704
#define WS_OFF UW_F
#define SMEM_BYTES ((UW_F + 240) * 4)  // 211,776 B

// ---------------- build helper ----------------
template<int MUL, int IRR, int KOFF, int IBASE>
static __device__ __forceinline__ void build_chunk(const float* __restrict__ up,
                                                   const float* __restrict__ ws,
                                                   float* __restrict__ uw, int tid) {
    for (int idx = tid; idx < 729 * IRR; idx += 512) {
        int ab  = idx / (9 * IRR);
        int rem = idx - ab * 9 * IRR;
        int j   = rem / IRR;
        int il  = rem - j * IRR;
        const float* ub = up + ((ab * 9 + j) * MUL) * IRR + il;
        float uv[MUL];
        #pragma unroll
        for (int k = 0; k < MUL; k++) uv[k] = __ldg(ub + k * IRR);
        float acc[8];
        #pragma unroll
        for (int c = 0; c < 8; c++) acc[c] = 0.f;
        #pragma unroll
        for (int k = 0; k < MUL; k++) {
            const float* wr = ws + (KOFF + k) * 8;
            #pragma unroll
            for (int c = 0; c < 8; c++) acc[c] += uv[k] * wr[c];
        }
        int e = ab * 9 + IBASE + il;
        #pragma unroll
        for (int c = 0; c < 8; c++) {
            const int hc = (4 - (c & 3)) & 3;
            int pos = (e >= hc) ? (e - hc) : (729 - hc + e);
            uw[c * CHSTR + j * JSTR + pos] = acc[c];
        }
    }
}

// ---------------- main kernel ----------------
// grid = (C/8, S), 512 threads = 16 warps: warp -> channel (wid>>1), half (wid&1).
// 4 nodes/group; lane covers a 4-element quad; f32x2 accs (E,E+1)/(E+2,E+3);
// uw via aligned LDS.128; outputs via STG.128 streaming stores.
__global__ __launch_bounds__(512, 1)
void mace_kernel(const float* __restrict__ nf,
                 const float* __restrict__ u0, const float* __restrict__ u1,
                 const float* __restrict__ u2,
                 const float* __restrict__ w0, const float* __restrict__ w1,
                 const float* __restrict__ w2,
                 float* __restrict__ out, int C) {
    extern __shared__ float sm[];
    float* uw = sm;
    float* ws = sm + WS_OFF;

    const int s = blockIdx.y;
    const int m = g_segCount[s];
    if (m == 0) return;             // CTA-uniform, before any barrier
    const int c0 = blockIdx.x * CT;
    const int segBase = g_segStart[s];
    const int tid = threadIdx.x;

    // ---- stage scaled species weights: ws[kglobal][c] ----
    if (tid < 240) {
        int kg = tid >> 3, c = tid & 7;
        const float* wp; int k; float scale; int mul;
        if (kg < 7)       { wp = w0; k = kg;      scale = 0.61478815f; mul = 7;  }
        else if (kg < 18) { wp = w1; k = kg - 7;  scale = 0.54910049f; mul = 11; }
        else              { wp = w2; k = kg - 18; scale = 0.53728497f; mul = 12; }
        ws[tid] = wp[((size_t)s * mul + k) * C + (c0 + c)] * scale;
    }
    __syncthreads();

    // ---- build uw (shifted layout) ----
    build_chunk<7, 1, 0, 0>(u0, ws, uw, tid);
    build_chunk<11, 3, 7, 1>(u1, ws, uw, tid);
    build_chunk<12, 5, 18, 4>(u2, ws, uw, tid);
    __syncthreads();

    // ---- main loop ----
    const int lane = tid & 31;
    const int wid  = tid >> 5;          // 0..15
    const int cw   = wid >> 1;          // channel in tile
    const int q    = wid & 1;           // node-group half
    const int crow = c0 + cw;
    const float* uwC = uw + cw * CHSTR;
    const int h  = (4 - (crow & 3)) & 3;  // warp-uniform phase
    const int Kq = (729 - h) >> 2;        // full quads
    const int nL = 729 - 4 * Kq;          // leftover scalars (head+tail, <=5)

    const int groups = (m + 3) >> 2;
    for (int g = q; g < groups; g += 2) {
        // gather 36 x-values (4 nodes x 9 j): v0 = el 0..31, v1 = el 32..35
        int n0 = lane / 9, j0 = lane - n0 * 9;
        int idx0 = g * 4 + n0;
        if (idx0 >= m) idx0 = m - 1;               // clamp: safe read, store masked
        int nid = g_order[segBase + idx0];
        float v0 = nf[((size_t)nid * C + crow) * 9 + j0];
        float v1 = 0.f;
        if (lane < 4) {
            int idx1 = g * 4 + 3;
            if (idx1 >= m) idx1 = m - 1;
            v1 = nf[((size_t)g_order[segBase + idx1] * C + crow) * 9 + (5 + lane)];
        }

        unsigned o[4];
        bool valid[4];
        #pragma unroll
        for (int nd = 0; nd < 4; nd++) {
            int n4 = __shfl_sync(0xffffffffu, nid, nd * 9);
            valid[nd] = (g * 4 + nd) < m;
            o[nd] = (unsigned)(n4 * C + crow) * 729u;
        }

        // dup-packed x: xd[nd][j] = (x, x)
        ull xd[4][9];
        #pragma unroll
        for (int nd = 0; nd < 4; nd++) {
            #pragma unroll
            for (int j = 0; j < 9; j++) {
                int el = nd * 9 + j;
                float xv = (el < 32) ? __shfl_sync(0xffffffffu, v0, el)
                                     : __shfl_sync(0xffffffffu, v1, el - 32);
                xd[nd][j] = pk2(xv);
            }
        }

        // body: quads q = it*32 + lane, elements E = h + 4q
        #pragma unroll 1
        for (int it = 0; it < 6; it++) {
            int qi = it * 32 + lane;
            bool act = qi < Kq;
            int qc = act ? qi : 0;
            int soff = 4 * qc;
            ull aA[4] = {0ull, 0ull, 0ull, 0ull};   // (E, E+1)
            ull aB[4] = {0ull, 0ull, 0ull, 0ull};   // (E+2, E+3)
            #pragma unroll
            for (int j = 0; j < 9; j++) {
                ulonglong2 uv = *reinterpret_cast<const ulonglong2*>(uwC + j * JSTR + soff);
                fma2(aA[0], uv.x, xd[0][j]);  fma2(aB[0], uv.y, xd[0][j]);
                fma2(aA[1], uv.x, xd[1][j]);  fma2(aB[1], uv.y, xd[1][j]);
                fma2(aA[2], uv.x, xd[2][j]);  fma2(aB[2], uv.y, xd[2][j]);
                fma2(aA[3], uv.x, xd[3][j]);  fma2(aB[3], uv.y, xd[3][j]);
            }
            int E = h + 4 * qc;
            #pragma unroll
            for (int nd = 0; nd < 4; nd++) {
                float4 f4;
                unpk2(aA[nd], f4.x, f4.y);
                unpk2(aB[nd], f4.z, f4.w);
                if (act && valid[nd])
                    __stcs(reinterpret_cast<float4*>(out + o[nd] + E), f4);
            }
        }

        // leftovers: head elements [0,h) and tail [h+4Kq, 729): nL lanes
        if (lane < nL) {
            int e   = (lane < h) ? lane : (4 * Kq + lane);
            int pos = (lane < h) ? (729 - h + lane) : (4 * Kq + lane - h);
            float b0 = 0.f, b1 = 0.f, b2 = 0.f, b3 = 0.f;
            #pragma unroll
            for (int j = 0; j < 9; j++) {
                float uvv = uwC[j * JSTR + pos];
                b0 += uvv * lo2(xd[0][j]);
                b1 += uvv * lo2(xd[1][j]);
                b2 += uvv * lo2(xd[2][j]);
                b3 += uvv * lo2(xd[3][j]);
            }
            if (valid[0]) __stcs(out + o[0] + e, b0);
            if (valid[1]) __stcs(out + o[1] + e, b1);
            if (valid[2]) __stcs(out + o[2] + e, b2);
            if (valid[3]) __stcs(out + o[3] + e, b3);
        }
    }
}

// ---------------- launch ----------------
extern "C" void kernel_launch(void* const* d_in, const int* in_sizes, int n_in,
                              void* d_out, int out_size) {
    const float *nf = nullptr, *u0 = nullptr, *u1 = nullptr, *u2 = nullptr;
    const float *w0 = nullptr, *w1 = nullptr, *w2 = nullptr;
    const int* index = nullptr;
    int N = 0, nf_sz = 0, w0_sz = 0;
    for (int i = 0; i < n_in; i++) {
        int sz = in_sizes[i];
        switch (sz) {
            case 5103:    u0 = (const float*)d_in[i]; break;
            case 24057:   u1 = (const float*)d_in[i]; break;
            case 43740:   u2 = (const float*)d_in[i]; break;
            case 44800:   w0 = (const float*)d_in[i]; w0_sz = sz; break;
            case 70400:   w1 = (const float*)d_in[i]; break;
            case 76800:   w2 = (const float*)d_in[i]; break;
            case 2048:    index = (const int*)d_in[i]; N = sz; break;
            case 2359296: nf = (const float*)d_in[i]; nf_sz = sz; break;
            default: break;
        }
    }
    if (!nf || !index || !u0 || !u1 || !u2 || !w0 || !w1 || !w2) return;

    const int C = nf_sz / (N * 9);        // 128
    const int S = w0_sz / (7 * C);        // 50

    group_kernel<<<1, 256>>>(index, N);

    cudaFuncSetAttribute(mace_kernel,
                         cudaFuncAttributeMaxDynamicSharedMemorySize, SMEM_BYTES);
    dim3 grid(C / CT, S);
    mace_kernel<<<grid, 512, SMEM_BYTES>>>(nf, u0, u1, u2, w0, w1, w2,
                                           (float*)d_out, C);
}